// round 4
// baseline (speedup 1.0000x reference)
#include <cuda_runtime.h>
#include <math.h>

#define NB 16
#define CCH 512

// Layer output lengths (VALID conv): floor((L-k)/s)+1
#define T0 6399   // 32000, k10 s5
#define T1 1598   // k8 s4
#define T2 798    // k4 s2
#define T3 398
#define T4 198

// ---------------- pooled scratch (single static device allocation) ----------------
#define P0_ELEMS ((size_t)NB * CCH * T0)
#define P1_ELEMS ((size_t)NB * CCH * T1)
#define F_ELEMS  ((size_t)NB * CCH * T4)
#define C_ELEMS  ((size_t)NB * 512 * 512)

#define OFF_P0  ((size_t)0)
#define OFF_P1  (OFF_P0 + P0_ELEMS + 4096)
#define OFF_FX  (OFF_P1 + P1_ELEMS + 4096)
#define OFF_FY  (OFF_FX + F_ELEMS)
#define OFF_SX  (OFF_FY + F_ELEMS)
#define OFF_SY  (OFF_SX + NB * CCH)
#define POOL_TOTAL (OFF_SY + NB * CCH + 4096)

#define OFF_CXY (OFF_P0)
#define OFF_CYX (OFF_CXY + C_ELEMS)
#define OFF_CXX (OFF_CYX + C_ELEMS)
#define OFF_CYY (OFF_CXX + C_ELEMS)

__device__ float  d_pool[POOL_TOTAL];
__device__ float  d_Wt1[4096 * 512];
__device__ float  d_Wt2[2048 * 512];
__device__ float  d_Wt3[2048 * 512];
__device__ float  d_Wt4[2048 * 512];
__device__ double d_stats[2 * NB];
__device__ float2 d_murs[NB];
__device__ float  d_w[3 * NB];

// ---------------- conv layer 0 (cin = 1, k=10, s=5) ----------------
__global__ void conv0_k(const float* __restrict__ wav, const float* __restrict__ W0,
                        float* __restrict__ out) {
    __shared__ float Ws[5120];
    int tid = threadIdx.x;  // 128
    for (int e = tid; e < 5120; e += 128) Ws[e] = W0[e];
    __syncthreads();
    int b = blockIdx.y;
    int t = blockIdx.x * 128 + tid;
    if (t >= T0) return;
    float w[10];
    const float* wp = wav + (size_t)b * 32000 + t * 5;
#pragma unroll
    for (int j = 0; j < 10; j++) w[j] = wp[j];
    float* op = out + (size_t)b * CCH * T0 + t;
    for (int co = 0; co < 512; co++) {
        float acc = 0.f;
#pragma unroll
        for (int j = 0; j < 10; j++) acc = fmaf(Ws[co * 10 + j], w[j], acc);
        op[(size_t)co * T0] = acc;
    }
}

// ---------------- weight transpose: W[co][ci][j] -> Wt[kk][co] ----------------
__global__ void transpose_k(const float* __restrict__ W, float* __restrict__ Wt, int K) {
    int idx = blockIdx.x * 256 + threadIdx.x;
    if (idx >= K * 512) return;
    int co = idx & 511, kk = idx >> 9;
    Wt[idx] = W[co * K + kk];
}

// ---------------- generic conv as implicit-im2col SGEMM ----------------
template <int KW, int SS, int CICH>
__global__ __launch_bounds__(256) void conv_gemm(const float* __restrict__ in,
                                                 const float* __restrict__ wt,
                                                 float* __restrict__ out,
                                                 int Tin, int Tout) {
    constexpr int SPAN = 127 * SS + KW;
    constexpr int KK = CICH * KW;  // 32
    __shared__ float Ws[KK][128];
    __shared__ float Is[CICH][SPAN];
    int tid = threadIdx.x;
    int tx = tid & 15, ty = tid >> 4;
    int b = blockIdx.z;
    int coBase = blockIdx.y * 128;
    int t0 = blockIdx.x * 128;
    const float* inB = in + (size_t)b * 512 * Tin;
    int tIn0 = t0 * SS;
    float acc[8][8];
#pragma unroll
    for (int v = 0; v < 8; v++)
#pragma unroll
        for (int u = 0; u < 8; u++) acc[v][u] = 0.f;

    for (int ci0 = 0; ci0 < 512; ci0 += CICH) {
#pragma unroll
        for (int q = 0; q < KK * 128 / 256; q++) {
            int e = tid + q * 256;
            int r = e >> 7, c = e & 127;
            Ws[r][c] = wt[(ci0 * KW + r) * 512 + coBase + c];
        }
        for (int e = tid; e < CICH * SPAN; e += 256) {
            int ci = e / SPAN, col = e - ci * SPAN;
            Is[ci][col] = inB[(size_t)(ci0 + ci) * Tin + tIn0 + col];
        }
        __syncthreads();
#pragma unroll
        for (int ci = 0; ci < CICH; ci++) {
#pragma unroll
            for (int j = 0; j < KW; j++) {
                float a[8], bb[8];
#pragma unroll
                for (int v = 0; v < 8; v++) a[v] = Ws[ci * KW + j][ty + 16 * v];
#pragma unroll
                for (int u = 0; u < 8; u++) bb[u] = Is[ci][(tx + 16 * u) * SS + j];
#pragma unroll
                for (int v = 0; v < 8; v++)
#pragma unroll
                    for (int u = 0; u < 8; u++) acc[v][u] = fmaf(a[v], bb[u], acc[v][u]);
            }
        }
        __syncthreads();
    }
    float* outB = out + (size_t)b * 512 * Tout;
#pragma unroll
    for (int v = 0; v < 8; v++) {
        int co = coBase + ty + 16 * v;
#pragma unroll
        for (int u = 0; u < 8; u++) {
            int t = t0 + tx + 16 * u;
            if (t < Tout) outB[(size_t)co * Tout + t] = acc[v][u];
        }
    }
}

// ---------------- group-norm stats (sum, sumsq per batch, double) ----------------
__global__ void zero_stats_k(double* stats) {
    if (threadIdx.x < 32) stats[threadIdx.x] = 0.0;
}

__global__ void stats_k(const float* __restrict__ in, double* stats, int L) {
    __shared__ double s1[256], s2[256];
    int b = blockIdx.x;
    int cs = (L + gridDim.y - 1) / gridDim.y;
    int start = blockIdx.y * cs;
    int end = min(L, start + cs);
    const float* p = in + (size_t)b * L;
    double s = 0.0, q = 0.0;
    for (int i = start + threadIdx.x; i < end; i += 256) {
        double v = (double)p[i];
        s += v;
        q += v * v;
    }
    s1[threadIdx.x] = s;
    s2[threadIdx.x] = q;
    __syncthreads();
    for (int st = 128; st > 0; st >>= 1) {
        if (threadIdx.x < st) {
            s1[threadIdx.x] += s1[threadIdx.x + st];
            s2[threadIdx.x] += s2[threadIdx.x + st];
        }
        __syncthreads();
    }
    if (threadIdx.x == 0) {
        atomicAdd(&stats[2 * b], s1[0]);
        atomicAdd(&stats[2 * b + 1], s2[0]);
    }
}

__global__ void statsfin_k(const double* stats, float2* murs, int L) {
    int i = threadIdx.x;
    if (i < NB) {
        double mu = stats[2 * i] / (double)L;
        double var = stats[2 * i + 1] / (double)L - mu * mu;
        double rs = 1.0 / sqrt(var + 1e-5);
        murs[i] = make_float2((float)mu, (float)rs);
    }
}

__global__ void norm_k(float* __restrict__ buf, float* __restrict__ outp,
                       const float* __restrict__ g, const float* __restrict__ be,
                       const float2* __restrict__ murs, int T) {
    long long total = (long long)NB * CCH * T;
    long long idx = (long long)blockIdx.x * 256 + threadIdx.x;
    if (idx >= total) return;
    int b = (int)(idx / ((long long)CCH * T));
    int c = (int)((idx / T) % CCH);
    float2 mr = murs[b];
    float v = (buf[idx] - mr.x) * mr.y * g[c] + be[c];
    outp[idx] = fmaxf(v, 0.f);
}

// ---------------- feature squared norms ----------------
__global__ void sqnorm_k(const float* __restrict__ f, float* __restrict__ s) {
    int idx = blockIdx.x * 256 + threadIdx.x;
    if (idx >= NB * CCH) return;
    const float* p = f + (size_t)idx * T4;
    float acc = 0.f;
    for (int d = 0; d < T4; d++) acc = fmaf(p[d], p[d], acc);
    s[idx] = acc;
}

// ---------------- cost matrix ----------------
__global__ __launch_bounds__(256) void cost_k(const float* __restrict__ A,
                                              const float* __restrict__ Bf,
                                              const float* __restrict__ sa,
                                              const float* __restrict__ sb,
                                              float* __restrict__ Co) {
    __shared__ float As[64][17], Bs[64][17];
    int b = blockIdx.z;
    const float* Ab = A + (size_t)b * 512 * T4;
    const float* Bb = Bf + (size_t)b * 512 * T4;
    int n0 = blockIdx.y * 64, m0 = blockIdx.x * 64;
    int tid = threadIdx.x;
    int rn = tid >> 4, cm = tid & 15;
    float acc[4][4];
#pragma unroll
    for (int i = 0; i < 4; i++)
#pragma unroll
        for (int j = 0; j < 4; j++) acc[i][j] = 0.f;
    for (int d0 = 0; d0 < T4; d0 += 16) {
#pragma unroll
        for (int q = 0; q < 4; q++) {
            int e = tid + q * 256;
            int r = e >> 4, dd = e & 15;
            As[r][dd] = (d0 + dd < T4) ? Ab[(size_t)(n0 + r) * T4 + d0 + dd] : 0.f;
            Bs[r][dd] = (d0 + dd < T4) ? Bb[(size_t)(m0 + r) * T4 + d0 + dd] : 0.f;
        }
        __syncthreads();
#pragma unroll
        for (int dd = 0; dd < 16; dd++) {
            float a[4], bb[4];
#pragma unroll
            for (int i = 0; i < 4; i++) a[i] = As[rn * 4 + i][dd];
#pragma unroll
            for (int j = 0; j < 4; j++) bb[j] = Bs[cm * 4 + j][dd];
#pragma unroll
            for (int i = 0; i < 4; i++)
#pragma unroll
                for (int j = 0; j < 4; j++) acc[i][j] = fmaf(a[i], bb[j], acc[i][j]);
        }
        __syncthreads();
    }
    const float* sab = sa + b * 512;
    const float* sbb = sb + b * 512;
    float* Cb = Co + (size_t)b * 512 * 512;
#pragma unroll
    for (int i = 0; i < 4; i++) {
        int n = n0 + rn * 4 + i;
#pragma unroll
        for (int j = 0; j < 4; j++) {
            int m = m0 + cm * 4 + j;
            Cb[(size_t)n * 512 + m] = 0.5f * fmaxf(sab[n] + sbb[m] - 2.f * acc[i][j], 0.f);
        }
    }
}

// ---------------- sinkhorn (log-domain, 50 iters) ----------------
__global__ __launch_bounds__(512) void sinkhorn_k(const float* __restrict__ Cxy,
                                                  const float* __restrict__ Cyx,
                                                  const float* __restrict__ Cxx,
                                                  const float* __restrict__ Cyy,
                                                  float* __restrict__ w) {
    __shared__ float fs[512], gs[512];
    int b = blockIdx.x, ot = blockIdx.y;
    size_t off = (size_t)b * 512 * 512;
    const float *Cg, *Cf;
    if (ot == 0) { Cg = Cxy + off; Cf = Cyx + off; }
    else if (ot == 1) { Cg = Cxx + off; Cf = Cg; }
    else { Cg = Cyy + off; Cf = Cg; }
    int tid = threadIdx.x;
    fs[tid] = 0.f;
    gs[tid] = 0.f;
    __syncthreads();
    const float LA = -6.2383246250395075f;  // -log(512)
    const float EPS = 0.0025f, IEPS = 400.f;
    for (int it = 0; it < 50; it++) {
        {
            const float* cp = Cg + tid;
            float M = -3.4e38f;
            for (int n = 0; n < 512; n += 8) {
                float v[8];
#pragma unroll
                for (int i = 0; i < 8; i++) v[i] = fs[n + i] - cp[(size_t)(n + i) << 9];
#pragma unroll
                for (int i = 0; i < 8; i++) M = fmaxf(M, v[i]);
            }
            float S = 0.f;
            for (int n = 0; n < 512; n += 8) {
                float v[8];
#pragma unroll
                for (int i = 0; i < 8; i++) v[i] = fs[n + i] - cp[(size_t)(n + i) << 9];
#pragma unroll
                for (int i = 0; i < 8; i++) S += __expf((v[i] - M) * IEPS);
            }
            gs[tid] = -EPS * (LA + __logf(S)) - M;
        }
        __syncthreads();
        {
            const float* cp = Cf + tid;
            float M = -3.4e38f;
            for (int m = 0; m < 512; m += 8) {
                float v[8];
#pragma unroll
                for (int i = 0; i < 8; i++) v[i] = gs[m + i] - cp[(size_t)(m + i) << 9];
#pragma unroll
                for (int i = 0; i < 8; i++) M = fmaxf(M, v[i]);
            }
            float S = 0.f;
            for (int m = 0; m < 512; m += 8) {
                float v[8];
#pragma unroll
                for (int i = 0; i < 8; i++) v[i] = gs[m + i] - cp[(size_t)(m + i) << 9];
#pragma unroll
                for (int i = 0; i < 8; i++) S += __expf((v[i] - M) * IEPS);
            }
            fs[tid] = -EPS * (LA + __logf(S)) - M;
        }
        __syncthreads();
    }
    fs[tid] += gs[tid];
    __syncthreads();
    for (int s = 256; s > 0; s >>= 1) {
        if (tid < s) fs[tid] += fs[tid + s];
        __syncthreads();
    }
    if (tid == 0) w[ot * 16 + b] = fs[0] * (1.f / 512.f);
}

__global__ void final_k(const float* __restrict__ w, float* __restrict__ out) {
    int b = threadIdx.x;
    if (b < NB) out[b] = w[b] - 0.5f * (w[16 + b] + w[32 + b]);
}

// ---------------- host driver ----------------
static void normseq(float* buf, int T, const float* g, const float* be, float* outp,
                    double* statsp, float2* mursp) {
    zero_stats_k<<<1, 32>>>(statsp);
    int L = CCH * T;
    stats_k<<<dim3(16, 48), 256>>>(buf, statsp, L);
    statsfin_k<<<1, 32>>>(statsp, mursp, L);
    long long total = (long long)NB * CCH * T;
    norm_k<<<(unsigned)((total + 255) / 256), 256>>>(buf, outp, g, be, mursp, T);
}

extern "C" void kernel_launch(void* const* d_in, const int* in_sizes, int n_in,
                              void* d_out, int out_size) {
    (void)out_size;
    const float* y_hat = (const float*)d_in[0];
    const float* y     = (const float*)d_in[1];
    const float* W[5];
    const float* g[5];
    const float* be[5];

    // Input layout detection:
    //   setup_inputs() dict order (interleaved): y_hat, y, W0,g0,b0, W1,g1,b1, ...
    //     -> in_sizes[3] == 512
    //   reference-signature order (flat): y_hat, y, W0..W4, g0..g4, b0..b4
    //     -> in_sizes[3] > 1024 (W1 = 512*512*8)
    if (n_in >= 17 && in_sizes[3] <= 1024) {
        for (int i = 0; i < 5; i++) {
            W[i]  = (const float*)d_in[2 + 3 * i];
            g[i]  = (const float*)d_in[3 + 3 * i];
            be[i] = (const float*)d_in[4 + 3 * i];
        }
    } else {
        for (int i = 0; i < 5; i++) {
            W[i]  = (const float*)d_in[2 + i];
            g[i]  = (const float*)d_in[7 + i];
            be[i] = (const float*)d_in[12 + i];
        }
    }
    float* out = (float*)d_out;

    float *pool, *Wt1, *Wt2, *Wt3, *Wt4, *wv;
    double* stats;
    float2* murs;
    cudaGetSymbolAddress((void**)&pool, d_pool);
    cudaGetSymbolAddress((void**)&Wt1, d_Wt1);
    cudaGetSymbolAddress((void**)&Wt2, d_Wt2);
    cudaGetSymbolAddress((void**)&Wt3, d_Wt3);
    cudaGetSymbolAddress((void**)&Wt4, d_Wt4);
    cudaGetSymbolAddress((void**)&stats, d_stats);
    cudaGetSymbolAddress((void**)&murs, d_murs);
    cudaGetSymbolAddress((void**)&wv, d_w);

    float* P0  = pool + OFF_P0;
    float* P1  = pool + OFF_P1;
    float* fx  = pool + OFF_FX;
    float* fy  = pool + OFF_FY;
    float* sx  = pool + OFF_SX;
    float* sy  = pool + OFF_SY;
    float* Cxy = pool + OFF_CXY;
    float* Cyx = pool + OFF_CYX;
    float* Cxx = pool + OFF_CXX;
    float* Cyy = pool + OFF_CYY;

    transpose_k<<<4096 * 512 / 256, 256>>>(W[1], Wt1, 4096);
    transpose_k<<<2048 * 512 / 256, 256>>>(W[2], Wt2, 2048);
    transpose_k<<<2048 * 512 / 256, 256>>>(W[3], Wt3, 2048);
    transpose_k<<<2048 * 512 / 256, 256>>>(W[4], Wt4, 2048);

    for (int s = 0; s < 2; s++) {
        const float* wav = s ? y : y_hat;
        float* feat = s ? fy : fx;
        conv0_k<<<dim3((T0 + 127) / 128, NB), 128>>>(wav, W[0], P0);
        normseq(P0, T0, g[0], be[0], P0, stats, murs);
        conv_gemm<8, 4, 4><<<dim3((T1 + 127) / 128, 4, NB), 256>>>(P0, Wt1, P1, T0, T1);
        normseq(P1, T1, g[1], be[1], P1, stats, murs);
        conv_gemm<4, 2, 8><<<dim3((T2 + 127) / 128, 4, NB), 256>>>(P1, Wt2, P0, T1, T2);
        normseq(P0, T2, g[2], be[2], P0, stats, murs);
        conv_gemm<4, 2, 8><<<dim3((T3 + 127) / 128, 4, NB), 256>>>(P0, Wt3, P1, T2, T3);
        normseq(P1, T3, g[3], be[3], P1, stats, murs);
        conv_gemm<4, 2, 8><<<dim3((T4 + 127) / 128, 4, NB), 256>>>(P1, Wt4, P0, T3, T4);
        normseq(P0, T4, g[4], be[4], feat, stats, murs);
    }

    sqnorm_k<<<(NB * CCH + 255) / 256, 256>>>(fx, sx);
    sqnorm_k<<<(NB * CCH + 255) / 256, 256>>>(fy, sy);

    cost_k<<<dim3(8, 8, NB), 256>>>(fx, fy, sx, sy, Cxy);
    cost_k<<<dim3(8, 8, NB), 256>>>(fy, fx, sy, sx, Cyx);
    cost_k<<<dim3(8, 8, NB), 256>>>(fx, fx, sx, sx, Cxx);
    cost_k<<<dim3(8, 8, NB), 256>>>(fy, fy, sy, sy, Cyy);

    sinkhorn_k<<<dim3(NB, 3), 512>>>(Cxy, Cyx, Cxx, Cyy, wv);
    final_k<<<1, 32>>>(wv, out);
}